// round 8
// baseline (speedup 1.0000x reference)
#include <cuda_runtime.h>
#include <cstdint>

// Problem constants
#define NB   8
#define CIN  16
#define LL   1024
#define DDIM 7
#define SZ   112     // CIN*DDIM
#define HH   16
#define DP   8       // padded head dim
#define SPLIT 8
#define KCH  (LL / SPLIT)   // 128 keys per block
#define NSLOT 128    // 16 heads * 8 padded cols

// Scratch
__device__ float g_q[NB * HH * LL * DP];   // q pre-scaled by log2(e)/32
__device__ float g_k[NB * HH * LL * DP];
__device__ float g_v[NB * HH * LL * DP];
__device__ float g_part[SPLIT * NB * HH * LL * DP];
__device__ float g_wt[3][SZ * NSLOT];      // W transposed+paired: [f][slot]
__device__ float g_bt[3][NSLOT];           // bias in slot layout

// ---------------- f32x2 packed helpers ----------------
using u64 = unsigned long long;

__device__ __forceinline__ u64 pk2(float lo, float hi) {
    u64 r; asm("mov.b64 %0,{%1,%2};" : "=l"(r) : "f"(lo), "f"(hi)); return r;
}
__device__ __forceinline__ u64 dup2(float v) {
    u64 r; asm("mov.b64 %0,{%1,%1};" : "=l"(r) : "f"(v)); return r;
}
__device__ __forceinline__ void up2(u64 v, float& lo, float& hi) {
    asm("mov.b64 {%0,%1},%2;" : "=f"(lo), "=f"(hi) : "l"(v));
}
__device__ __forceinline__ u64 fma2(u64 a, u64 b, u64 c) {
    u64 d; asm("fma.rn.f32x2 %0,%1,%2,%3;" : "=l"(d) : "l"(a), "l"(b), "l"(c)); return d;
}
__device__ __forceinline__ u64 mul2(u64 a, u64 b) {
    u64 d; asm("mul.rn.f32x2 %0,%1,%2;" : "=l"(d) : "l"(a), "l"(b)); return d;
}
__device__ __forceinline__ u64 add2(u64 a, u64 b) {
    u64 d; asm("add.rn.f32x2 %0,%1,%2;" : "=l"(d) : "l"(a), "l"(b)); return d;
}
__device__ __forceinline__ float ex2f(float a) {
    float d; asm("ex2.approx.f32 %0,%1;" : "=f"(d) : "f"(a)); return d;
}

// ---------------- Kernel 0: pack W (once) ----------------
// 3 blocks x 256 threads. Scattered transpose reads happen HERE once (via smem),
// so the 384 gemm blocks can fill with pure coalesced copies.
// m==0 (Wq): fold softmax scale log2(e)/32 into weights+bias.
__global__ void __launch_bounds__(256)
pack_w(const float* __restrict__ Wq, const float* __restrict__ bq,
       const float* __restrict__ Wk, const float* __restrict__ bk,
       const float* __restrict__ Wv, const float* __restrict__ bv)
{
    __shared__ float wsm[SZ * SZ];
    const int m = blockIdx.x;
    const float* W = (m == 0) ? Wq : ((m == 1) ? Wk : Wv);
    const float* b = (m == 0) ? bq : ((m == 1) ? bk : bv);
    const float scale = (m == 0) ? 0.04508422002778011f : 1.0f;
    const int tid = threadIdx.x;

    for (int i = tid; i < SZ * SZ; i += 256)
        wsm[i] = W[i];
    __syncthreads();

    // g_wt[m][f*128+slot] = W[(lh*7+j)][f] * scale  (j==7 -> 0 pad)
    for (int i = tid; i < SZ * NSLOT; i += 256) {
        int slot = i & 127;
        int f    = i >> 7;
        int lh = slot >> 3, j = slot & 7;
        g_wt[m][i] = (j < 7) ? wsm[(lh * 7 + j) * SZ + f] * scale : 0.0f;
    }
    if (tid < NSLOT) {
        int lh = tid >> 3, j = tid & 7;
        g_bt[m][tid] = (j < 7) ? b[lh * 7 + j] * scale : 0.0f;
    }
}

// ---------------- Kernel 1: QKV projection ----------------
// 384 blocks x 512 threads, 2 blocks/SM (87KB smem).
// Fill phase is now FULLY COALESCED (g_wt pre-packed). Warp = head:
// W reads are broadcast LDS.128 pairs, x reads are 2-way float2.
#define LT    64
#define XSTR  66
#define GEMM_SMEM ((SZ * XSTR + SZ * NSLOT) * 4)

__global__ void __launch_bounds__(512, 2)
qkv_gemm(const float* __restrict__ x)
{
    extern __shared__ float sm[];
    float* xs = sm;              // [112 f][66 l]
    float* ws = sm + SZ * XSTR;  // [112 f][128 slot]

    const int tid = threadIdx.x;
    const int bid = blockIdx.x;
    const int m   = bid >> 7;          // 0..2
    const int rem = bid & 127;
    const int n   = rem >> 4;          // 0..7
    const int lt  = rem & 15;          // l-tile 0..15
    const int l0  = lt * LT;

    float* og = (m == 0) ? g_q : ((m == 1) ? g_k : g_v);

    // Coalesced float4 copy of packed W (3584 float4)
    {
        const float4* src = (const float4*)g_wt[m];
        float4* dst = (float4*)ws;
        for (int i = tid; i < SZ * NSLOT / 4; i += 512)
            dst[i] = src[i];
    }

    // x [c][l][dd] -> xs[f=c*7+dd][l]  (coalesced gmem reads)
    const float* xb = x + ((size_t)n * CIN * LL + l0) * DDIM;
    for (int i = tid; i < CIN * LT * DDIM; i += 512) {
        int c = i / (LT * DDIM);
        int r = i - c * (LT * DDIM);
        float v = xb[(size_t)c * LL * DDIM + r];
        int l = r / DDIM;
        int dd = r - l * DDIM;
        xs[(c * DDIM + dd) * XSTR + l] = v;
    }
    __syncthreads();

    const int h    = tid >> 5;        // warp = head
    const int lane = tid & 31;
    const int r0   = lane * 2;        // row pair

    // acc[row][colpair]: pairs (c0,c1)(c2,c3)(c4,c5)(c6,pad); bias from g_bt.
    u64 acc[2][4];
    {
        const u64* bt = (const u64*)&g_bt[m][h * 8];
        u64 b0 = bt[0], b1 = bt[1], b2 = bt[2], b3 = bt[3];
        acc[0][0] = b0; acc[0][1] = b1; acc[0][2] = b2; acc[0][3] = b3;
        acc[1][0] = b0; acc[1][1] = b1; acc[1][2] = b2; acc[1][3] = b3;
    }

    const float* xr = &xs[r0];
    const float* wr = &ws[h * 8];

#pragma unroll 4
    for (int f = 0; f < SZ; ++f) {
        float2 xv = *(const float2*)&xr[f * XSTR];
        ulonglong2 wA = *(const ulonglong2*)&wr[f * NSLOT];      // (c0,c1),(c2,c3)
        ulonglong2 wB = *(const ulonglong2*)&wr[f * NSLOT + 4];  // (c4,c5),(c6,pad)
        u64 x0d = dup2(xv.x);
        u64 x1d = dup2(xv.y);
        acc[0][0] = fma2(x0d, wA.x, acc[0][0]);
        acc[0][1] = fma2(x0d, wA.y, acc[0][1]);
        acc[0][2] = fma2(x0d, wB.x, acc[0][2]);
        acc[0][3] = fma2(x0d, wB.y, acc[0][3]);
        acc[1][0] = fma2(x1d, wA.x, acc[1][0]);
        acc[1][1] = fma2(x1d, wA.y, acc[1][1]);
        acc[1][2] = fma2(x1d, wB.x, acc[1][2]);
        acc[1][3] = fma2(x1d, wB.y, acc[1][3]);
    }

    // Store [n][h][l][8]; pad col 7 is exactly 0 (0-bias + 0-weights).
    float* op = og + (((size_t)n * HH + h) * LL + l0 + r0) * DP;
#pragma unroll
    for (int rr = 0; rr < 2; ++rr) {
        float c0, c1, c2, c3, c4, c5, c6, c7;
        up2(acc[rr][0], c0, c1);
        up2(acc[rr][1], c2, c3);
        up2(acc[rr][2], c4, c5);
        up2(acc[rr][3], c6, c7);
        float4* o = (float4*)(op + rr * DP);
        o[0] = make_float4(c0, c1, c2, c3);
        o[1] = make_float4(c4, c5, c6, c7);
    }
}

// ---------------- Kernel 2: key-split attention partials ----------------
__global__ void __launch_bounds__(256, 2)
attn_kernel()
{
    __shared__ u64 kd[KCH * 8];
    __shared__ u64 vd[KCH * 8];

    const int tid = threadIdx.x;
    const int bh  = blockIdx.x >> 3;
    const int ks  = blockIdx.x & 7;
    const int kbase = ks * KCH;

    if (tid < KCH) {
        const float4* kp = (const float4*)(g_k + ((size_t)bh * LL + kbase + tid) * DP);
        float4 a = kp[0], c = kp[1];
        u64* o = kd + tid * 8;
        o[0] = dup2(a.x); o[1] = dup2(a.y); o[2] = dup2(a.z); o[3] = dup2(a.w);
        o[4] = dup2(c.x); o[5] = dup2(c.y); o[6] = dup2(c.z); o[7] = 0ull;
    } else {
        int t = tid - KCH;
        const float4* vp = (const float4*)(g_v + ((size_t)bh * LL + kbase + t) * DP);
        float4 a = vp[0], c = vp[1];
        u64* o = vd + t * 8;
        o[0] = dup2(a.x); o[1] = dup2(a.y); o[2] = dup2(a.z); o[3] = dup2(a.w);
        o[4] = dup2(c.x); o[5] = dup2(c.y); o[6] = dup2(c.z); o[7] = 0ull;
    }

    const int r0 = tid * 4;
    const float* qg = g_q + ((size_t)bh * LL + r0) * DP;
    u64 q0[7], q1[7];
    {
        float4 a0 = *(const float4*)(qg + 0);
        float4 a1 = *(const float4*)(qg + 4);
        float4 b0 = *(const float4*)(qg + 8);
        float4 b1 = *(const float4*)(qg + 12);
        float4 c0 = *(const float4*)(qg + 16);
        float4 c1 = *(const float4*)(qg + 20);
        float4 d0 = *(const float4*)(qg + 24);
        float4 d1 = *(const float4*)(qg + 28);
        q0[0] = pk2(a0.x, b0.x); q0[1] = pk2(a0.y, b0.y); q0[2] = pk2(a0.z, b0.z);
        q0[3] = pk2(a0.w, b0.w); q0[4] = pk2(a1.x, b1.x); q0[5] = pk2(a1.y, b1.y);
        q0[6] = pk2(a1.z, b1.z);
        q1[0] = pk2(c0.x, d0.x); q1[1] = pk2(c0.y, d0.y); q1[2] = pk2(c0.z, d0.z);
        q1[3] = pk2(c0.w, d0.w); q1[4] = pk2(c1.x, d1.x); q1[5] = pk2(c1.y, d1.y);
        q1[6] = pk2(c1.z, d1.z);
    }
    __syncthreads();

    u64 acc0[7], acc1[7];
    u64 S0 = dup2(0.0f), S1 = dup2(0.0f);
#pragma unroll
    for (int j = 0; j < 7; ++j) { acc0[j] = S0; acc1[j] = S0; }

#pragma unroll 4
    for (int key = 0; key < KCH; ++key) {
        ulonglong2 ka = *(const ulonglong2*)(kd + key * 8);
        ulonglong2 kb = *(const ulonglong2*)(kd + key * 8 + 2);
        ulonglong2 kc = *(const ulonglong2*)(kd + key * 8 + 4);
        ulonglong2 ke = *(const ulonglong2*)(kd + key * 8 + 6);

        u64 s0 = mul2(q0[0], ka.x);
        u64 s1 = mul2(q1[0], ka.x);
        s0 = fma2(q0[1], ka.y, s0); s1 = fma2(q1[1], ka.y, s1);
        s0 = fma2(q0[2], kb.x, s0); s1 = fma2(q1[2], kb.x, s1);
        s0 = fma2(q0[3], kb.y, s0); s1 = fma2(q1[3], kb.y, s1);
        s0 = fma2(q0[4], kc.x, s0); s1 = fma2(q1[4], kc.x, s1);
        s0 = fma2(q0[5], kc.y, s0); s1 = fma2(q1[5], kc.y, s1);
        s0 = fma2(q0[6], ke.x, s0); s1 = fma2(q1[6], ke.x, s1);

        float e0, e1, e2, e3;
        up2(s0, e0, e1);
        up2(s1, e2, e3);
        u64 p0 = pk2(ex2f(e0), ex2f(e1));
        u64 p1 = pk2(ex2f(e2), ex2f(e3));
        S0 = add2(S0, p0);
        S1 = add2(S1, p1);

        ulonglong2 va = *(const ulonglong2*)(vd + key * 8);
        ulonglong2 vb = *(const ulonglong2*)(vd + key * 8 + 2);
        ulonglong2 vc = *(const ulonglong2*)(vd + key * 8 + 4);
        ulonglong2 ve = *(const ulonglong2*)(vd + key * 8 + 6);

        acc0[0] = fma2(p0, va.x, acc0[0]); acc1[0] = fma2(p1, va.x, acc1[0]);
        acc0[1] = fma2(p0, va.y, acc0[1]); acc1[1] = fma2(p1, va.y, acc1[1]);
        acc0[2] = fma2(p0, vb.x, acc0[2]); acc1[2] = fma2(p1, vb.x, acc1[2]);
        acc0[3] = fma2(p0, vb.y, acc0[3]); acc1[3] = fma2(p1, vb.y, acc1[3]);
        acc0[4] = fma2(p0, vc.x, acc0[4]); acc1[4] = fma2(p1, vc.x, acc1[4]);
        acc0[5] = fma2(p0, vc.y, acc0[5]); acc1[5] = fma2(p1, vc.y, acc1[5]);
        acc0[6] = fma2(p0, ve.x, acc0[6]); acc1[6] = fma2(p1, ve.x, acc1[6]);
    }

    float* pp = g_part + (((size_t)(ks * NB * HH + bh)) * LL + r0) * DP;
    float lo[7], hi[7], sl, sh;
#pragma unroll
    for (int j = 0; j < 7; ++j) up2(acc0[j], lo[j], hi[j]);
    up2(S0, sl, sh);
    ((float4*)pp)[0] = make_float4(lo[0], lo[1], lo[2], lo[3]);
    ((float4*)pp)[1] = make_float4(lo[4], lo[5], lo[6], sl);
    ((float4*)pp)[2] = make_float4(hi[0], hi[1], hi[2], hi[3]);
    ((float4*)pp)[3] = make_float4(hi[4], hi[5], hi[6], sh);
#pragma unroll
    for (int j = 0; j < 7; ++j) up2(acc1[j], lo[j], hi[j]);
    up2(S1, sl, sh);
    ((float4*)pp)[4] = make_float4(lo[0], lo[1], lo[2], lo[3]);
    ((float4*)pp)[5] = make_float4(lo[4], lo[5], lo[6], sl);
    ((float4*)pp)[6] = make_float4(hi[0], hi[1], hi[2], hi[3]);
    ((float4*)pp)[7] = make_float4(hi[4], hi[5], hi[6], sh);
}

// ---------------- Kernel 3: combine partials + normalize ----------------
__global__ void __launch_bounds__(256)
reduce_kernel(float* __restrict__ out)
{
    const int qi = blockIdx.x * 256 + threadIdx.x;   // 131072 queries
    const int bh = qi >> 10;
    const int l  = qi & 1023;

    float a0 = 0, a1 = 0, a2 = 0, a3 = 0, a4 = 0, a5 = 0, a6 = 0, S = 0;
#pragma unroll
    for (int ks = 0; ks < SPLIT; ++ks) {
        const float4* p = (const float4*)(g_part +
            (((size_t)(ks * NB * HH + bh)) * LL + l) * DP);
        float4 a = p[0], b = p[1];
        a0 += a.x; a1 += a.y; a2 += a.z; a3 += a.w;
        a4 += b.x; a5 += b.y; a6 += b.z; S  += b.w;
    }
    float inv = 1.0f / S;
    float* op = out + (size_t)qi * DDIM;
    op[0] = a0 * inv; op[1] = a1 * inv; op[2] = a2 * inv;
    op[3] = a3 * inv; op[4] = a4 * inv; op[5] = a5 * inv;
    op[6] = a6 * inv;
}

// ---------------- launch ----------------
extern "C" void kernel_launch(void* const* d_in, const int* in_sizes, int n_in,
                              void* d_out, int out_size)
{
    const float* x  = (const float*)d_in[0];
    const float* Wq = (const float*)d_in[1];
    const float* bq = (const float*)d_in[2];
    const float* Wk = (const float*)d_in[3];
    const float* bk = (const float*)d_in[4];
    const float* Wv = (const float*)d_in[5];
    const float* bv = (const float*)d_in[6];

    cudaFuncSetAttribute(qkv_gemm, cudaFuncAttributeMaxDynamicSharedMemorySize, GEMM_SMEM);
    cudaFuncSetAttribute(qkv_gemm, cudaFuncAttributePreferredSharedMemoryCarveout, 100);
    cudaFuncSetAttribute(attn_kernel, cudaFuncAttributePreferredSharedMemoryCarveout, 100);

    pack_w<<<3, 256>>>(Wq, bq, Wk, bk, Wv, bv);
    qkv_gemm<<<384, 512, GEMM_SMEM>>>(x);
    attn_kernel<<<NB * HH * SPLIT, 256>>>();
    reduce_kernel<<<NB * HH * LL / 256, 256>>>((float*)d_out);
}

// round 9
// speedup vs baseline: 1.0654x; 1.0654x over previous
#include <cuda_runtime.h>
#include <cstdint>

// Problem constants
#define NB   8
#define CIN  16
#define LL   1024
#define DDIM 7
#define SZ   112     // CIN*DDIM
#define HH   16
#define DP   8       // padded head dim
#define SPLIT 4
#define KCH  (LL / SPLIT)   // 256 keys per block

// Scratch: Q/K/V in [n][h][l][8] (4MB each), partials [ks][bh][l][8]
__device__ float g_q[NB * HH * LL * DP];   // q pre-scaled by log2(e)/32
__device__ float g_k[NB * HH * LL * DP];
__device__ float g_v[NB * HH * LL * DP];
__device__ float g_part[SPLIT * NB * HH * LL * DP];

// ---------------- f32x2 packed helpers ----------------
using u64 = unsigned long long;

__device__ __forceinline__ u64 pk2(float lo, float hi) {
    u64 r; asm("mov.b64 %0,{%1,%2};" : "=l"(r) : "f"(lo), "f"(hi)); return r;
}
__device__ __forceinline__ u64 dup2(float v) {
    u64 r; asm("mov.b64 %0,{%1,%1};" : "=l"(r) : "f"(v)); return r;
}
__device__ __forceinline__ void up2(u64 v, float& lo, float& hi) {
    asm("mov.b64 {%0,%1},%2;" : "=f"(lo), "=f"(hi) : "l"(v));
}
__device__ __forceinline__ u64 fma2(u64 a, u64 b, u64 c) {
    u64 d; asm("fma.rn.f32x2 %0,%1,%2,%3;" : "=l"(d) : "l"(a), "l"(b), "l"(c)); return d;
}
__device__ __forceinline__ u64 mul2(u64 a, u64 b) {
    u64 d; asm("mul.rn.f32x2 %0,%1,%2;" : "=l"(d) : "l"(a), "l"(b)); return d;
}
__device__ __forceinline__ u64 add2(u64 a, u64 b) {
    u64 d; asm("add.rn.f32x2 %0,%1,%2;" : "=l"(d) : "l"(a), "l"(b)); return d;
}
__device__ __forceinline__ float ex2f(float a) {
    float d; asm("ex2.approx.f32 %0,%1;" : "=f"(d) : "f"(a)); return d;
}

// ---------------- Kernel 1: fused transpose + QKV projection (R4 best) ----------------
// grid (64, 3), 512 threads: bx -> (n, l-tile of 128), by -> Wq/Wk/Wv.
// xs_t[f][l] (stride 132), ws[c][f] (stride 116, float4 over f).
#define SXT 132
#define SWS 116
#define GEMM_SMEM ((SZ * SXT + SZ * SWS) * 4)

__global__ void __launch_bounds__(512, 1)
qkv_gemm(const float* __restrict__ x,
         const float* __restrict__ Wq, const float* __restrict__ bq,
         const float* __restrict__ Wk, const float* __restrict__ bk,
         const float* __restrict__ Wv, const float* __restrict__ bv)
{
    extern __shared__ float sm[];
    float* xs = sm;             // [112 f][SXT]
    float* ws = sm + SZ * SXT;  // [112 c][SWS]

    const int tid = threadIdx.x;
    const int m = blockIdx.y;
    const float* W = (m == 0) ? Wq : ((m == 1) ? Wk : Wv);
    const float* b = (m == 0) ? bq : ((m == 1) ? bk : bv);
    float* og = (m == 0) ? g_q : ((m == 1) ? g_k : g_v);

    const int n  = blockIdx.x >> 3;
    const int l0 = (blockIdx.x & 7) << 7;

    for (int i = tid; i < SZ * SZ; i += 512)
        ws[(i / SZ) * SWS + (i % SZ)] = W[i];

    // x [c][l][dd] -> xs[f=c*7+dd][l]
    const float* xb = x + ((size_t)n * CIN * LL + l0) * DDIM;
    for (int i = tid; i < CIN * 128 * DDIM; i += 512) {
        int c = i / (128 * DDIM);
        int r = i - c * (128 * DDIM);
        float v = xb[(size_t)c * LL * DDIM + r];
        int l = r / DDIM;
        int dd = r - l * DDIM;
        xs[(c * DDIM + dd) * SXT + l] = v;
    }
    __syncthreads();

    const int tx = tid & 15;    // head / col group
    const int ty = tid >> 4;    // row group (0..31)
    const int c0 = tx * 7;
    const int r0 = ty * 4;

    u64 acc[2][7];
#pragma unroll
    for (int j = 0; j < 7; ++j) {
        u64 bb = dup2(__ldg(&b[c0 + j]));
        acc[0][j] = bb; acc[1][j] = bb;
    }

#pragma unroll 2
    for (int f0 = 0; f0 < SZ; f0 += 4) {
        float4 xa[4];
#pragma unroll
        for (int ff = 0; ff < 4; ++ff)
            xa[ff] = *(const float4*)&xs[(f0 + ff) * SXT + r0];
        float4 w4[7];
#pragma unroll
        for (int j = 0; j < 7; ++j)
            w4[j] = *(const float4*)&ws[(c0 + j) * SWS + f0];

#pragma unroll
        for (int ff = 0; ff < 4; ++ff) {
            u64 xp0 = pk2(xa[ff].x, xa[ff].y);
            u64 xp1 = pk2(xa[ff].z, xa[ff].w);
            const float wv[7] = {
                (ff == 0) ? w4[0].x : (ff == 1) ? w4[0].y : (ff == 2) ? w4[0].z : w4[0].w,
                (ff == 0) ? w4[1].x : (ff == 1) ? w4[1].y : (ff == 2) ? w4[1].z : w4[1].w,
                (ff == 0) ? w4[2].x : (ff == 1) ? w4[2].y : (ff == 2) ? w4[2].z : w4[2].w,
                (ff == 0) ? w4[3].x : (ff == 1) ? w4[3].y : (ff == 2) ? w4[3].z : w4[3].w,
                (ff == 0) ? w4[4].x : (ff == 1) ? w4[4].y : (ff == 2) ? w4[4].z : w4[4].w,
                (ff == 0) ? w4[5].x : (ff == 1) ? w4[5].y : (ff == 2) ? w4[5].z : w4[5].w,
                (ff == 0) ? w4[6].x : (ff == 1) ? w4[6].y : (ff == 2) ? w4[6].z : w4[6].w };
#pragma unroll
            for (int j = 0; j < 7; ++j) {
                u64 wd = dup2(wv[j]);
                acc[0][j] = fma2(xp0, wd, acc[0][j]);
                acc[1][j] = fma2(xp1, wd, acc[1][j]);
            }
        }
    }

    // For Q, fold in log2(e)/32 so attention needs no per-key scale.
    if (m == 0) {
        const u64 SC = dup2(0.04508422002778011f);
#pragma unroll
        for (int j = 0; j < 7; ++j) {
            acc[0][j] = mul2(acc[0][j], SC);
            acc[1][j] = mul2(acc[1][j], SC);
        }
    }

    // Store [n][h][l][8], pad with 0.
    float* op = og + (((size_t)n * HH + tx) * LL + l0 + r0) * DP;
#pragma unroll
    for (int p = 0; p < 2; ++p) {
        float lo[7], hi[7];
#pragma unroll
        for (int j = 0; j < 7; ++j) up2(acc[p][j], lo[j], hi[j]);
        float4* o0 = (float4*)(op + (2 * p) * DP);
        float4* o1 = (float4*)(op + (2 * p + 1) * DP);
        o0[0] = make_float4(lo[0], lo[1], lo[2], lo[3]);
        o0[1] = make_float4(lo[4], lo[5], lo[6], 0.0f);
        o1[0] = make_float4(hi[0], hi[1], hi[2], hi[3]);
        o1[1] = make_float4(hi[4], hi[5], hi[6], 0.0f);
    }
}

// ---------------- Kernel 2: key-split attention partials ----------------
// grid 512 = (bh, key-chunk of 256). 256 threads, 4 query rows/thread as
// 2 f32x2 pairs. K/V pre-duplicated as f32x2 in smem (32KB), 2 blocks/SM.
// SPLIT=4: prologue amortized over 2x keys, partial traffic halved.
__global__ void __launch_bounds__(256, 2)
attn_kernel()
{
    __shared__ u64 kd[KCH * 8];
    __shared__ u64 vd[KCH * 8];

    const int tid = threadIdx.x;
    const int bh  = blockIdx.x >> 2;
    const int ks  = blockIdx.x & 3;
    const int kbase = ks * KCH;

    // Each thread loads one K row and one V row (256 rows each, coalesced float4)
    {
        const float4* kp = (const float4*)(g_k + ((size_t)bh * LL + kbase + tid) * DP);
        float4 a = kp[0], c = kp[1];
        u64* o = kd + tid * 8;
        o[0] = dup2(a.x); o[1] = dup2(a.y); o[2] = dup2(a.z); o[3] = dup2(a.w);
        o[4] = dup2(c.x); o[5] = dup2(c.y); o[6] = dup2(c.z); o[7] = 0ull;
        const float4* vp = (const float4*)(g_v + ((size_t)bh * LL + kbase + tid) * DP);
        float4 av = vp[0], cv = vp[1];
        u64* ov = vd + tid * 8;
        ov[0] = dup2(av.x); ov[1] = dup2(av.y); ov[2] = dup2(av.z); ov[3] = dup2(av.w);
        ov[4] = dup2(cv.x); ov[5] = dup2(cv.y); ov[6] = dup2(cv.z); ov[7] = 0ull;
    }

    const int r0 = tid * 4;
    const float* qg = g_q + ((size_t)bh * LL + r0) * DP;
    u64 q0[7], q1[7];
    {
        float4 a0 = *(const float4*)(qg + 0);
        float4 a1 = *(const float4*)(qg + 4);
        float4 b0 = *(const float4*)(qg + 8);
        float4 b1 = *(const float4*)(qg + 12);
        float4 c0 = *(const float4*)(qg + 16);
        float4 c1 = *(const float4*)(qg + 20);
        float4 d0 = *(const float4*)(qg + 24);
        float4 d1 = *(const float4*)(qg + 28);
        q0[0] = pk2(a0.x, b0.x); q0[1] = pk2(a0.y, b0.y); q0[2] = pk2(a0.z, b0.z);
        q0[3] = pk2(a0.w, b0.w); q0[4] = pk2(a1.x, b1.x); q0[5] = pk2(a1.y, b1.y);
        q0[6] = pk2(a1.z, b1.z);
        q1[0] = pk2(c0.x, d0.x); q1[1] = pk2(c0.y, d0.y); q1[2] = pk2(c0.z, d0.z);
        q1[3] = pk2(c0.w, d0.w); q1[4] = pk2(c1.x, d1.x); q1[5] = pk2(c1.y, d1.y);
        q1[6] = pk2(c1.z, d1.z);
    }
    __syncthreads();

    u64 acc0[7], acc1[7];
    u64 S0 = dup2(0.0f), S1 = dup2(0.0f);
#pragma unroll
    for (int j = 0; j < 7; ++j) { acc0[j] = S0; acc1[j] = S0; }

#pragma unroll 4
    for (int key = 0; key < KCH; ++key) {
        ulonglong2 ka = *(const ulonglong2*)(kd + key * 8);
        ulonglong2 kb = *(const ulonglong2*)(kd + key * 8 + 2);
        ulonglong2 kc = *(const ulonglong2*)(kd + key * 8 + 4);
        ulonglong2 ke = *(const ulonglong2*)(kd + key * 8 + 6);

        u64 s0 = mul2(q0[0], ka.x);
        u64 s1 = mul2(q1[0], ka.x);
        s0 = fma2(q0[1], ka.y, s0); s1 = fma2(q1[1], ka.y, s1);
        s0 = fma2(q0[2], kb.x, s0); s1 = fma2(q1[2], kb.x, s1);
        s0 = fma2(q0[3], kb.y, s0); s1 = fma2(q1[3], kb.y, s1);
        s0 = fma2(q0[4], kc.x, s0); s1 = fma2(q1[4], kc.x, s1);
        s0 = fma2(q0[5], kc.y, s0); s1 = fma2(q1[5], kc.y, s1);
        s0 = fma2(q0[6], ke.x, s0); s1 = fma2(q1[6], ke.x, s1);

        float e0, e1, e2, e3;
        up2(s0, e0, e1);
        up2(s1, e2, e3);
        u64 p0 = pk2(ex2f(e0), ex2f(e1));
        u64 p1 = pk2(ex2f(e2), ex2f(e3));
        S0 = add2(S0, p0);
        S1 = add2(S1, p1);

        ulonglong2 va = *(const ulonglong2*)(vd + key * 8);
        ulonglong2 vb = *(const ulonglong2*)(vd + key * 8 + 2);
        ulonglong2 vc = *(const ulonglong2*)(vd + key * 8 + 4);
        ulonglong2 ve = *(const ulonglong2*)(vd + key * 8 + 6);

        acc0[0] = fma2(p0, va.x, acc0[0]); acc1[0] = fma2(p1, va.x, acc1[0]);
        acc0[1] = fma2(p0, va.y, acc0[1]); acc1[1] = fma2(p1, va.y, acc1[1]);
        acc0[2] = fma2(p0, vb.x, acc0[2]); acc1[2] = fma2(p1, vb.x, acc1[2]);
        acc0[3] = fma2(p0, vb.y, acc0[3]); acc1[3] = fma2(p1, vb.y, acc1[3]);
        acc0[4] = fma2(p0, vc.x, acc0[4]); acc1[4] = fma2(p1, vc.x, acc1[4]);
        acc0[5] = fma2(p0, vc.y, acc0[5]); acc1[5] = fma2(p1, vc.y, acc1[5]);
        acc0[6] = fma2(p0, ve.x, acc0[6]); acc1[6] = fma2(p1, ve.x, acc1[6]);
    }

    // Write partials: [ks][bh][l][8] = {acc0..6, S}
    float* pp = g_part + (((size_t)(ks * NB * HH + bh)) * LL + r0) * DP;
    float lo[7], hi[7], sl, sh;
#pragma unroll
    for (int j = 0; j < 7; ++j) up2(acc0[j], lo[j], hi[j]);
    up2(S0, sl, sh);
    ((float4*)pp)[0] = make_float4(lo[0], lo[1], lo[2], lo[3]);
    ((float4*)pp)[1] = make_float4(lo[4], lo[5], lo[6], sl);
    ((float4*)pp)[2] = make_float4(hi[0], hi[1], hi[2], hi[3]);
    ((float4*)pp)[3] = make_float4(hi[4], hi[5], hi[6], sh);
#pragma unroll
    for (int j = 0; j < 7; ++j) up2(acc1[j], lo[j], hi[j]);
    up2(S1, sl, sh);
    ((float4*)pp)[4] = make_float4(lo[0], lo[1], lo[2], lo[3]);
    ((float4*)pp)[5] = make_float4(lo[4], lo[5], lo[6], sl);
    ((float4*)pp)[6] = make_float4(hi[0], hi[1], hi[2], hi[3]);
    ((float4*)pp)[7] = make_float4(hi[4], hi[5], hi[6], sh);
}

// ---------------- Kernel 3: combine partials + normalize ----------------
__global__ void __launch_bounds__(256)
reduce_kernel(float* __restrict__ out)
{
    const int qi = blockIdx.x * 256 + threadIdx.x;   // 131072 queries
    const int bh = qi >> 10;
    const int l  = qi & 1023;

    float a0 = 0, a1 = 0, a2 = 0, a3 = 0, a4 = 0, a5 = 0, a6 = 0, S = 0;
#pragma unroll
    for (int ks = 0; ks < SPLIT; ++ks) {
        const float4* p = (const float4*)(g_part +
            (((size_t)(ks * NB * HH + bh)) * LL + l) * DP);
        float4 a = p[0], b = p[1];
        a0 += a.x; a1 += a.y; a2 += a.z; a3 += a.w;
        a4 += b.x; a5 += b.y; a6 += b.z; S  += b.w;
    }
    float inv = 1.0f / S;
    float* op = out + (size_t)qi * DDIM;
    op[0] = a0 * inv; op[1] = a1 * inv; op[2] = a2 * inv;
    op[3] = a3 * inv; op[4] = a4 * inv; op[5] = a5 * inv;
    op[6] = a6 * inv;
}

// ---------------- launch ----------------
extern "C" void kernel_launch(void* const* d_in, const int* in_sizes, int n_in,
                              void* d_out, int out_size)
{
    const float* x  = (const float*)d_in[0];
    const float* Wq = (const float*)d_in[1];
    const float* bq = (const float*)d_in[2];
    const float* Wk = (const float*)d_in[3];
    const float* bk = (const float*)d_in[4];
    const float* Wv = (const float*)d_in[5];
    const float* bv = (const float*)d_in[6];

    cudaFuncSetAttribute(qkv_gemm, cudaFuncAttributeMaxDynamicSharedMemorySize, GEMM_SMEM);
    cudaFuncSetAttribute(qkv_gemm, cudaFuncAttributePreferredSharedMemoryCarveout, 100);
    cudaFuncSetAttribute(attn_kernel, cudaFuncAttributePreferredSharedMemoryCarveout, 100);

    qkv_gemm<<<dim3(64, 3), 512, GEMM_SMEM>>>(x, Wq, bq, Wk, bk, Wv, bv);
    attn_kernel<<<NB * HH * SPLIT, 256>>>();
    reduce_kernel<<<NB * HH * LL / 256, 256>>>((float*)d_out);
}

// round 10
// speedup vs baseline: 1.2079x; 1.1338x over previous
#include <cuda_runtime.h>
#include <cstdint>

// Problem constants
#define NB   8
#define CIN  16
#define LL   1024
#define DDIM 7
#define SZ   112     // CIN*DDIM
#define HH   16
#define DP   8       // padded head dim
#define SPLIT 8
#define KCH  (LL / SPLIT)   // 128 keys per block

// Scratch: Q/K/V in [n][h][l][8] (4MB each), partials [ks][bh][l][8]
__device__ float g_q[NB * HH * LL * DP];   // q pre-scaled by log2(e)/32
__device__ float g_k[NB * HH * LL * DP];
__device__ float g_v[NB * HH * LL * DP];
__device__ float g_part[SPLIT * NB * HH * LL * DP];

// ---------------- f32x2 packed helpers ----------------
using u64 = unsigned long long;

__device__ __forceinline__ u64 pk2(float lo, float hi) {
    u64 r; asm("mov.b64 %0,{%1,%2};" : "=l"(r) : "f"(lo), "f"(hi)); return r;
}
__device__ __forceinline__ u64 dup2(float v) {
    u64 r; asm("mov.b64 %0,{%1,%1};" : "=l"(r) : "f"(v)); return r;
}
__device__ __forceinline__ void up2(u64 v, float& lo, float& hi) {
    asm("mov.b64 {%0,%1},%2;" : "=f"(lo), "=f"(hi) : "l"(v));
}
__device__ __forceinline__ u64 fma2(u64 a, u64 b, u64 c) {
    u64 d; asm("fma.rn.f32x2 %0,%1,%2,%3;" : "=l"(d) : "l"(a), "l"(b), "l"(c)); return d;
}
__device__ __forceinline__ u64 mul2(u64 a, u64 b) {
    u64 d; asm("mul.rn.f32x2 %0,%1,%2;" : "=l"(d) : "l"(a), "l"(b)); return d;
}
__device__ __forceinline__ u64 add2(u64 a, u64 b) {
    u64 d; asm("add.rn.f32x2 %0,%1,%2;" : "=l"(d) : "l"(a), "l"(b)); return d;
}
__device__ __forceinline__ float ex2f(float a) {
    float d; asm("ex2.approx.f32 %0,%1;" : "=f"(d) : "f"(a)); return d;
}

// ---------------- Kernel 1: fused transpose + QKV projection ----------------
// R4 inner loop, l-tile 64: smem 82.4KB -> 2 blocks/SM -> 8 warps/SMSP resident.
// grid (128, 3), 256 threads: bx -> (n, l-tile of 64), by -> Wq/Wk/Wv.
// xs_t[f][l] (stride 68, 16B-aligned rows), ws[c][f] (stride 116, float4 over f).
#define SXT 68
#define SWS 116
#define GEMM_SMEM ((SZ * SXT + SZ * SWS) * 4)

__global__ void __launch_bounds__(256, 2)
qkv_gemm(const float* __restrict__ x,
         const float* __restrict__ Wq, const float* __restrict__ bq,
         const float* __restrict__ Wk, const float* __restrict__ bk,
         const float* __restrict__ Wv, const float* __restrict__ bv)
{
    extern __shared__ float sm[];
    float* xs = sm;             // [112 f][SXT]
    float* ws = sm + SZ * SXT;  // [112 c][SWS]

    const int tid = threadIdx.x;
    const int m = blockIdx.y;
    const float* W = (m == 0) ? Wq : ((m == 1) ? Wk : Wv);
    const float* b = (m == 0) ? bq : ((m == 1) ? bk : bv);
    float* og = (m == 0) ? g_q : ((m == 1) ? g_k : g_v);

    const int n  = blockIdx.x >> 4;          // 16 l-tiles per n
    const int l0 = (blockIdx.x & 15) << 6;

    for (int i = tid; i < SZ * SZ; i += 256)
        ws[(i / SZ) * SWS + (i % SZ)] = W[i];

    // x [c][l][dd] -> xs[f=c*7+dd][l]
    const float* xb = x + ((size_t)n * CIN * LL + l0) * DDIM;
    for (int i = tid; i < CIN * 64 * DDIM; i += 256) {
        int c = i / (64 * DDIM);
        int r = i - c * (64 * DDIM);
        float v = xb[(size_t)c * LL * DDIM + r];
        int l = r / DDIM;
        int dd = r - l * DDIM;
        xs[(c * DDIM + dd) * SXT + l] = v;
    }
    __syncthreads();

    const int tx = tid & 15;    // head / col group
    const int ty = tid >> 4;    // row group (0..15)
    const int c0 = tx * 7;
    const int r0 = ty * 4;

    u64 acc[2][7];
#pragma unroll
    for (int j = 0; j < 7; ++j) {
        u64 bb = dup2(__ldg(&b[c0 + j]));
        acc[0][j] = bb; acc[1][j] = bb;
    }

#pragma unroll 2
    for (int f0 = 0; f0 < SZ; f0 += 4) {
        float4 xa[4];
#pragma unroll
        for (int ff = 0; ff < 4; ++ff)
            xa[ff] = *(const float4*)&xs[(f0 + ff) * SXT + r0];
        float4 w4[7];
#pragma unroll
        for (int j = 0; j < 7; ++j)
            w4[j] = *(const float4*)&ws[(c0 + j) * SWS + f0];

#pragma unroll
        for (int ff = 0; ff < 4; ++ff) {
            u64 xp0 = pk2(xa[ff].x, xa[ff].y);
            u64 xp1 = pk2(xa[ff].z, xa[ff].w);
            const float wv[7] = {
                (ff == 0) ? w4[0].x : (ff == 1) ? w4[0].y : (ff == 2) ? w4[0].z : w4[0].w,
                (ff == 0) ? w4[1].x : (ff == 1) ? w4[1].y : (ff == 2) ? w4[1].z : w4[1].w,
                (ff == 0) ? w4[2].x : (ff == 1) ? w4[2].y : (ff == 2) ? w4[2].z : w4[2].w,
                (ff == 0) ? w4[3].x : (ff == 1) ? w4[3].y : (ff == 2) ? w4[3].z : w4[3].w,
                (ff == 0) ? w4[4].x : (ff == 1) ? w4[4].y : (ff == 2) ? w4[4].z : w4[4].w,
                (ff == 0) ? w4[5].x : (ff == 1) ? w4[5].y : (ff == 2) ? w4[5].z : w4[5].w,
                (ff == 0) ? w4[6].x : (ff == 1) ? w4[6].y : (ff == 2) ? w4[6].z : w4[6].w };
#pragma unroll
            for (int j = 0; j < 7; ++j) {
                u64 wd = dup2(wv[j]);
                acc[0][j] = fma2(xp0, wd, acc[0][j]);
                acc[1][j] = fma2(xp1, wd, acc[1][j]);
            }
        }
    }

    // For Q, fold in log2(e)/32 so attention needs no per-key scale.
    if (m == 0) {
        const u64 SC = dup2(0.04508422002778011f);
#pragma unroll
        for (int j = 0; j < 7; ++j) {
            acc[0][j] = mul2(acc[0][j], SC);
            acc[1][j] = mul2(acc[1][j], SC);
        }
    }

    // Store [n][h][l][8], pad with 0.
    float* op = og + (((size_t)n * HH + tx) * LL + l0 + r0) * DP;
#pragma unroll
    for (int p = 0; p < 2; ++p) {
        float lo[7], hi[7];
#pragma unroll
        for (int j = 0; j < 7; ++j) up2(acc[p][j], lo[j], hi[j]);
        float4* o0 = (float4*)(op + (2 * p) * DP);
        float4* o1 = (float4*)(op + (2 * p + 1) * DP);
        o0[0] = make_float4(lo[0], lo[1], lo[2], lo[3]);
        o0[1] = make_float4(lo[4], lo[5], lo[6], 0.0f);
        o1[0] = make_float4(hi[0], hi[1], hi[2], hi[3]);
        o1[1] = make_float4(hi[4], hi[5], hi[6], 0.0f);
    }
}

// ---------------- Kernel 2: key-split attention partials (R4 exact) ----------------
__global__ void __launch_bounds__(256, 2)
attn_kernel()
{
    __shared__ u64 kd[KCH * 8];
    __shared__ u64 vd[KCH * 8];

    const int tid = threadIdx.x;
    const int bh  = blockIdx.x >> 3;
    const int ks  = blockIdx.x & 7;
    const int kbase = ks * KCH;

    if (tid < KCH) {
        const float4* kp = (const float4*)(g_k + ((size_t)bh * LL + kbase + tid) * DP);
        float4 a = kp[0], c = kp[1];
        u64* o = kd + tid * 8;
        o[0] = dup2(a.x); o[1] = dup2(a.y); o[2] = dup2(a.z); o[3] = dup2(a.w);
        o[4] = dup2(c.x); o[5] = dup2(c.y); o[6] = dup2(c.z); o[7] = 0ull;
    } else {
        int t = tid - KCH;
        const float4* vp = (const float4*)(g_v + ((size_t)bh * LL + kbase + t) * DP);
        float4 a = vp[0], c = vp[1];
        u64* o = vd + t * 8;
        o[0] = dup2(a.x); o[1] = dup2(a.y); o[2] = dup2(a.z); o[3] = dup2(a.w);
        o[4] = dup2(c.x); o[5] = dup2(c.y); o[6] = dup2(c.z); o[7] = 0ull;
    }

    const int r0 = tid * 4;
    const float* qg = g_q + ((size_t)bh * LL + r0) * DP;
    u64 q0[7], q1[7];
    {
        float4 a0 = *(const float4*)(qg + 0);
        float4 a1 = *(const float4*)(qg + 4);
        float4 b0 = *(const float4*)(qg + 8);
        float4 b1 = *(const float4*)(qg + 12);
        float4 c0 = *(const float4*)(qg + 16);
        float4 c1 = *(const float4*)(qg + 20);
        float4 d0 = *(const float4*)(qg + 24);
        float4 d1 = *(const float4*)(qg + 28);
        q0[0] = pk2(a0.x, b0.x); q0[1] = pk2(a0.y, b0.y); q0[2] = pk2(a0.z, b0.z);
        q0[3] = pk2(a0.w, b0.w); q0[4] = pk2(a1.x, b1.x); q0[5] = pk2(a1.y, b1.y);
        q0[6] = pk2(a1.z, b1.z);
        q1[0] = pk2(c0.x, d0.x); q1[1] = pk2(c0.y, d0.y); q1[2] = pk2(c0.z, d0.z);
        q1[3] = pk2(c0.w, d0.w); q1[4] = pk2(c1.x, d1.x); q1[5] = pk2(c1.y, d1.y);
        q1[6] = pk2(c1.z, d1.z);
    }
    __syncthreads();

    u64 acc0[7], acc1[7];
    u64 S0 = dup2(0.0f), S1 = dup2(0.0f);
#pragma unroll
    for (int j = 0; j < 7; ++j) { acc0[j] = S0; acc1[j] = S0; }

#pragma unroll 4
    for (int key = 0; key < KCH; ++key) {
        ulonglong2 ka = *(const ulonglong2*)(kd + key * 8);
        ulonglong2 kb = *(const ulonglong2*)(kd + key * 8 + 2);
        ulonglong2 kc = *(const ulonglong2*)(kd + key * 8 + 4);
        ulonglong2 ke = *(const ulonglong2*)(kd + key * 8 + 6);

        u64 s0 = mul2(q0[0], ka.x);
        u64 s1 = mul2(q1[0], ka.x);
        s0 = fma2(q0[1], ka.y, s0); s1 = fma2(q1[1], ka.y, s1);
        s0 = fma2(q0[2], kb.x, s0); s1 = fma2(q1[2], kb.x, s1);
        s0 = fma2(q0[3], kb.y, s0); s1 = fma2(q1[3], kb.y, s1);
        s0 = fma2(q0[4], kc.x, s0); s1 = fma2(q1[4], kc.x, s1);
        s0 = fma2(q0[5], kc.y, s0); s1 = fma2(q1[5], kc.y, s1);
        s0 = fma2(q0[6], ke.x, s0); s1 = fma2(q1[6], ke.x, s1);

        float e0, e1, e2, e3;
        up2(s0, e0, e1);
        up2(s1, e2, e3);
        u64 p0 = pk2(ex2f(e0), ex2f(e1));
        u64 p1 = pk2(ex2f(e2), ex2f(e3));
        S0 = add2(S0, p0);
        S1 = add2(S1, p1);

        ulonglong2 va = *(const ulonglong2*)(vd + key * 8);
        ulonglong2 vb = *(const ulonglong2*)(vd + key * 8 + 2);
        ulonglong2 vc = *(const ulonglong2*)(vd + key * 8 + 4);
        ulonglong2 ve = *(const ulonglong2*)(vd + key * 8 + 6);

        acc0[0] = fma2(p0, va.x, acc0[0]); acc1[0] = fma2(p1, va.x, acc1[0]);
        acc0[1] = fma2(p0, va.y, acc0[1]); acc1[1] = fma2(p1, va.y, acc1[1]);
        acc0[2] = fma2(p0, vb.x, acc0[2]); acc1[2] = fma2(p1, vb.x, acc1[2]);
        acc0[3] = fma2(p0, vb.y, acc0[3]); acc1[3] = fma2(p1, vb.y, acc1[3]);
        acc0[4] = fma2(p0, vc.x, acc0[4]); acc1[4] = fma2(p1, vc.x, acc1[4]);
        acc0[5] = fma2(p0, vc.y, acc0[5]); acc1[5] = fma2(p1, vc.y, acc1[5]);
        acc0[6] = fma2(p0, ve.x, acc0[6]); acc1[6] = fma2(p1, ve.x, acc1[6]);
    }

    float* pp = g_part + (((size_t)(ks * NB * HH + bh)) * LL + r0) * DP;
    float lo[7], hi[7], sl, sh;
#pragma unroll
    for (int j = 0; j < 7; ++j) up2(acc0[j], lo[j], hi[j]);
    up2(S0, sl, sh);
    ((float4*)pp)[0] = make_float4(lo[0], lo[1], lo[2], lo[3]);
    ((float4*)pp)[1] = make_float4(lo[4], lo[5], lo[6], sl);
    ((float4*)pp)[2] = make_float4(hi[0], hi[1], hi[2], hi[3]);
    ((float4*)pp)[3] = make_float4(hi[4], hi[5], hi[6], sh);
#pragma unroll
    for (int j = 0; j < 7; ++j) up2(acc1[j], lo[j], hi[j]);
    up2(S1, sl, sh);
    ((float4*)pp)[4] = make_float4(lo[0], lo[1], lo[2], lo[3]);
    ((float4*)pp)[5] = make_float4(lo[4], lo[5], lo[6], sl);
    ((float4*)pp)[6] = make_float4(hi[0], hi[1], hi[2], hi[3]);
    ((float4*)pp)[7] = make_float4(hi[4], hi[5], hi[6], sh);
}

// ---------------- Kernel 3: combine partials + normalize ----------------
__global__ void __launch_bounds__(256)
reduce_kernel(float* __restrict__ out)
{
    const int qi = blockIdx.x * 256 + threadIdx.x;   // 131072 queries
    const int bh = qi >> 10;
    const int l  = qi & 1023;

    float a0 = 0, a1 = 0, a2 = 0, a3 = 0, a4 = 0, a5 = 0, a6 = 0, S = 0;
#pragma unroll
    for (int ks = 0; ks < SPLIT; ++ks) {
        const float4* p = (const float4*)(g_part +
            (((size_t)(ks * NB * HH + bh)) * LL + l) * DP);
        float4 a = p[0], b = p[1];
        a0 += a.x; a1 += a.y; a2 += a.z; a3 += a.w;
        a4 += b.x; a5 += b.y; a6 += b.z; S  += b.w;
    }
    float inv = 1.0f / S;
    float* op = out + (size_t)qi * DDIM;
    op[0] = a0 * inv; op[1] = a1 * inv; op[2] = a2 * inv;
    op[3] = a3 * inv; op[4] = a4 * inv; op[5] = a5 * inv;
    op[6] = a6 * inv;
}

// ---------------- launch ----------------
extern "C" void kernel_launch(void* const* d_in, const int* in_sizes, int n_in,
                              void* d_out, int out_size)
{
    const float* x  = (const float*)d_in[0];
    const float* Wq = (const float*)d_in[1];
    const float* bq = (const float*)d_in[2];
    const float* Wk = (const float*)d_in[3];
    const float* bk = (const float*)d_in[4];
    const float* Wv = (const float*)d_in[5];
    const float* bv = (const float*)d_in[6];

    cudaFuncSetAttribute(qkv_gemm, cudaFuncAttributeMaxDynamicSharedMemorySize, GEMM_SMEM);
    cudaFuncSetAttribute(qkv_gemm, cudaFuncAttributePreferredSharedMemoryCarveout, 100);
    cudaFuncSetAttribute(attn_kernel, cudaFuncAttributePreferredSharedMemoryCarveout, 100);

    qkv_gemm<<<dim3(128, 3), 256, GEMM_SMEM>>>(x, Wq, bq, Wk, bk, Wv, bv);
    attn_kernel<<<NB * HH * SPLIT, 256>>>();
    reduce_kernel<<<NB * HH * LL / 256, 256>>>((float*)d_out);
}